// round 5
// baseline (speedup 1.0000x reference)
#include <cuda_runtime.h>

#define NN 50000
#define NE 800000
#define C 64
#define CIN 16
#define NL 4
#define HSTEP 0.1f
#define EPSV 1e-3f

__device__ __align__(256) float g_Xn[NN * C];
__device__ __align__(256) float g_Z[NN * C];
__device__ __align__(256) float g_W[NN * C];
__device__ __align__(256) float g_U[NN * C];
__device__ __align__(256) float g_div[NN * C];           // running divergence (64ch)
__device__ __align__(256) float g_div16[NN * CIN];       // raw-xe divergence (16ch)
__device__ __align__(256) float g_ACC[(size_t)NE * CIN]; // per-edge close accum
__device__ __align__(256) float g_scr[6 * C];            // sA qA sW qW sU qU
__device__ __align__(256) float g_nrm[6 * C];            // mrH_A rH_A mrH_W rH_W mrH_U rH_U
__device__ __align__(256) float g_M2[CIN * CIN];         // KEclose@KEopen

__device__ __forceinline__ void red4(float* p, float x, float y, float z, float w) {
    asm volatile("red.global.add.v4.f32 [%0], {%1,%2,%3,%4};"
                 :: "l"(p), "f"(x), "f"(y), "f"(z), "f"(w) : "memory");
}

#define BFLY4(v, d)                                   \
    v.x += __shfl_xor_sync(0xffffffffu, v.x, d);      \
    v.y += __shfl_xor_sync(0xffffffffu, v.y, d);      \
    v.z += __shfl_xor_sync(0xffffffffu, v.z, d);      \
    v.w += __shfl_xor_sync(0xffffffffu, v.w, d);

__global__ void k_init() {
    int t = blockIdx.x * blockDim.x + threadIdx.x;
    if (t < NN * CIN) g_div16[t] = 0.f;
    if (t < 6 * C) g_scr[t] = 0.f;
}

// M2 = KEclose @ KEopen (16x16), 256 threads
__global__ void k_m2(const float* __restrict__ KEc, const float* __restrict__ KEo) {
    int t = threadIdx.x;
    int co = t >> 4, ci = t & 15;
    float s = 0.f;
#pragma unroll
    for (int k = 0; k < C; k++) s += KEc[co * C + k] * KEo[k * CIN + ci];
    g_M2[co * CIN + ci] = s;
}

// Xn[n][k] = sum_c KNopen[k][c] * in[c*count + n]
__global__ void k_open(const float* __restrict__ in, const float* __restrict__ K,
                       float* __restrict__ out, int count) {
    __shared__ __align__(16) float KT[CIN * C];
    for (int idx = threadIdx.x; idx < CIN * C; idx += blockDim.x) {
        int k = idx & (C - 1); int c = idx >> 6;
        KT[idx] = K[k * CIN + c];
    }
    __syncthreads();
    int n = blockIdx.x * blockDim.x + threadIdx.x;
    if (n >= count) return;
    float4 acc[C / 4];
#pragma unroll
    for (int q = 0; q < C / 4; q++) acc[q] = make_float4(0.f, 0.f, 0.f, 0.f);
#pragma unroll
    for (int c = 0; c < CIN; c++) {
        float v = __ldg(&in[(size_t)c * count + n]);
        const float4* w = (const float4*)&KT[c * C];
#pragma unroll
        for (int q = 0; q < C / 4; q++) {
            float4 t = w[q];
            acc[q].x += t.x * v; acc[q].y += t.y * v;
            acc[q].z += t.z * v; acc[q].w += t.w * v;
        }
    }
    float4* o = (float4*)&out[(size_t)n * C];
#pragma unroll
    for (int q = 0; q < C / 4; q++) o[q] = acc[q];
}

// scatter raw xe (channel-major [16,E]) into g_div16 [N][16]
__global__ void k_edge0(const float* __restrict__ xe, const int* __restrict__ iInd,
                        const int* __restrict__ jInd) {
    int e = blockIdx.x * blockDim.x + threadIdx.x;
    if (e >= NE) return;
    int i = __ldg(&iInd[e]);
    int j = __ldg(&jInd[e]);
    float a[CIN];
#pragma unroll
    for (int c = 0; c < CIN; c++) a[c] = __ldg(&xe[(size_t)c * NE + e]);
    float* di = &g_div16[(size_t)i * CIN];
    float* dj = &g_div16[(size_t)j * CIN];
#pragma unroll
    for (int k = 0; k < 4; k++)
        red4(di + k * 4, a[k * 4], a[k * 4 + 1], a[k * 4 + 2], a[k * 4 + 3]);
#pragma unroll
    for (int k = 0; k < 4; k++)
        red4(dj + k * 4, -a[k * 4], -a[k * 4 + 1], -a[k * 4 + 2], -a[k * 4 + 3]);
}

// Out[n][k] = sum_c M[k*CI+c]*In[n][c], 4 threads/node. soff>=0: fused stats.
template <int CI>
__global__ void k_mm4q(const float* __restrict__ In, const float* __restrict__ M,
                       float* __restrict__ Out, int count, int soff) {
    __shared__ __align__(16) float MT[CI * C];
    __shared__ __align__(16) float Tin[64 * CI];
    __shared__ float red[2 * C];
    int tid = threadIdx.x;
    for (int idx = tid; idx < CI * C; idx += 256) {
        int k = idx & (C - 1); int c = idx >> 6;
        MT[idx] = M[k * CI + c];
    }
    if (tid < 2 * C) red[tid] = 0.f;
    int nb = blockIdx.x * 64;
    const int F4 = 64 * CI / 4;
    const float4* In4 = (const float4*)In;
    int lim = count * (CI / 4);
    for (int idx = tid; idx < F4; idx += 256) {
        int g = nb * (CI / 4) + idx;
        ((float4*)Tin)[idx] = (g < lim) ? In4[g] : make_float4(0.f, 0.f, 0.f, 0.f);
    }
    __syncthreads();
    int q = tid & 3, nl = tid >> 2;
    int n = nb + nl;
    float4 a0 = make_float4(0.f, 0.f, 0.f, 0.f), a1 = a0, a2 = a0, a3 = a0;
    const float4* T4 = (const float4*)&Tin[nl * CI];
#pragma unroll
    for (int c4 = 0; c4 < CI / 4; c4++) {
        float4 v = T4[c4];
#pragma unroll
        for (int cc = 0; cc < 4; cc++) {
            float s = (cc == 0) ? v.x : (cc == 1) ? v.y : (cc == 2) ? v.z : v.w;
            const float4* w = (const float4*)&MT[(c4 * 4 + cc) * C + q * 16];
            float4 w0 = w[0], w1 = w[1], w2 = w[2], w3 = w[3];
            a0.x += w0.x * s; a0.y += w0.y * s; a0.z += w0.z * s; a0.w += w0.w * s;
            a1.x += w1.x * s; a1.y += w1.y * s; a1.z += w1.z * s; a1.w += w1.w * s;
            a2.x += w2.x * s; a2.y += w2.y * s; a2.z += w2.z * s; a2.w += w2.w * s;
            a3.x += w3.x * s; a3.y += w3.y * s; a3.z += w3.z * s; a3.w += w3.w * s;
        }
    }
    if (n < count) {
        float4* o = (float4*)&Out[(size_t)n * C + q * 16];
        o[0] = a0; o[1] = a1; o[2] = a2; o[3] = a3;
    }
    if (soff >= 0) {
        float4 s0 = a0, s1 = a1, s2 = a2, s3 = a3;
        float4 q0, q1, q2, q3;
        q0.x = a0.x * a0.x; q0.y = a0.y * a0.y; q0.z = a0.z * a0.z; q0.w = a0.w * a0.w;
        q1.x = a1.x * a1.x; q1.y = a1.y * a1.y; q1.z = a1.z * a1.z; q1.w = a1.w * a1.w;
        q2.x = a2.x * a2.x; q2.y = a2.y * a2.y; q2.z = a2.z * a2.z; q2.w = a2.w * a2.w;
        q3.x = a3.x * a3.x; q3.y = a3.y * a3.y; q3.z = a3.z * a3.z; q3.w = a3.w * a3.w;
#pragma unroll
        for (int d = 4; d < 32; d <<= 1) {
            BFLY4(s0, d) BFLY4(s1, d) BFLY4(s2, d) BFLY4(s3, d)
            BFLY4(q0, d) BFLY4(q1, d) BFLY4(q2, d) BFLY4(q3, d)
        }
        if ((tid & 31) < 4) {
            int ch = q * 16;
            atomicAdd(&red[ch + 0], s0.x);  atomicAdd(&red[ch + 1], s0.y);
            atomicAdd(&red[ch + 2], s0.z);  atomicAdd(&red[ch + 3], s0.w);
            atomicAdd(&red[ch + 4], s1.x);  atomicAdd(&red[ch + 5], s1.y);
            atomicAdd(&red[ch + 6], s1.z);  atomicAdd(&red[ch + 7], s1.w);
            atomicAdd(&red[ch + 8], s2.x);  atomicAdd(&red[ch + 9], s2.y);
            atomicAdd(&red[ch + 10], s2.z); atomicAdd(&red[ch + 11], s2.w);
            atomicAdd(&red[ch + 12], s3.x); atomicAdd(&red[ch + 13], s3.y);
            atomicAdd(&red[ch + 14], s3.z); atomicAdd(&red[ch + 15], s3.w);
            atomicAdd(&red[C + ch + 0], q0.x);  atomicAdd(&red[C + ch + 1], q0.y);
            atomicAdd(&red[C + ch + 2], q0.z);  atomicAdd(&red[C + ch + 3], q0.w);
            atomicAdd(&red[C + ch + 4], q1.x);  atomicAdd(&red[C + ch + 5], q1.y);
            atomicAdd(&red[C + ch + 6], q1.z);  atomicAdd(&red[C + ch + 7], q1.w);
            atomicAdd(&red[C + ch + 8], q2.x);  atomicAdd(&red[C + ch + 9], q2.y);
            atomicAdd(&red[C + ch + 10], q2.z); atomicAdd(&red[C + ch + 11], q2.w);
            atomicAdd(&red[C + ch + 12], q3.x); atomicAdd(&red[C + ch + 13], q3.y);
            atomicAdd(&red[C + ch + 14], q3.z); atomicAdd(&red[C + ch + 15], q3.w);
        }
        __syncthreads();
        if (tid < 2 * C) atomicAdd(&g_scr[soff + tid], red[tid]);
    }
}

// edge sweep A: per-channel sum/sumsq of y = Z[:,i]-Z[:,j]
__global__ void k_edgeA(const int* __restrict__ iInd, const int* __restrict__ jInd) {
    int t = blockIdx.x * blockDim.x + threadIdx.x;
    int lane = t & 15;
    int grp = t >> 4;
    int ngrp = (gridDim.x * blockDim.x) >> 4;
    float4 s = make_float4(0.f, 0.f, 0.f, 0.f);
    float4 q = make_float4(0.f, 0.f, 0.f, 0.f);
    for (int e = grp; e < NE; e += ngrp) {
        int i = __ldg(&iInd[e]);
        int j = __ldg(&jInd[e]);
        float4 a = __ldg((const float4*)&g_Z[(size_t)i * C + lane * 4]);
        float4 b = __ldg((const float4*)&g_Z[(size_t)j * C + lane * 4]);
        float yx = a.x - b.x, yy = a.y - b.y, yz = a.z - b.z, yw = a.w - b.w;
        s.x += yx; s.y += yy; s.z += yz; s.w += yw;
        q.x += yx * yx; q.y += yy * yy; q.z += yz * yz; q.w += yw * yw;
    }
    __shared__ float ss[C], sq[C];
    if (threadIdx.x < C) { ss[threadIdx.x] = 0.f; sq[threadIdx.x] = 0.f; }
    __syncthreads();
    int ch = lane * 4;
    atomicAdd(&ss[ch + 0], s.x); atomicAdd(&ss[ch + 1], s.y);
    atomicAdd(&ss[ch + 2], s.z); atomicAdd(&ss[ch + 3], s.w);
    atomicAdd(&sq[ch + 0], q.x); atomicAdd(&sq[ch + 1], q.y);
    atomicAdd(&sq[ch + 2], q.z); atomicAdd(&sq[ch + 3], q.w);
    __syncthreads();
    if (threadIdx.x < C) {
        atomicAdd(&g_scr[threadIdx.x], ss[threadIdx.x]);
        atomicAdd(&g_scr[C + threadIdx.x], sq[threadIdx.x]);
    }
}

// mrH = mean*rH, rH = H/sqrt(var+eps); zero consumed scr slots. 256 threads.
__global__ void k_scales(int which) {
    int c = threadIdx.x;
    if (which == 0) {
        if (c < C) {
            float s = g_scr[c], q = g_scr[C + c];
            float m = s / (float)NE;
            float rH = HSTEP / sqrtf(fmaxf(q - s * m, 0.f) + EPSV);
            g_nrm[c] = m * rH; g_nrm[C + c] = rH;
            s = g_scr[2 * C + c]; q = g_scr[3 * C + c];
            m = s / (float)NN;
            rH = HSTEP / sqrtf(fmaxf(q - s * m, 0.f) + EPSV);
            g_nrm[2 * C + c] = m * rH; g_nrm[3 * C + c] = rH;
        }
        __syncthreads();
        g_scr[c] = 0.f;
    } else {
        if (c < C) {
            float s = g_scr[4 * C + c], q = g_scr[5 * C + c];
            float m = s / (float)NN;
            float rH = HSTEP / sqrtf(fmaxf(q - s * m, 0.f) + EPSV);
            g_nrm[4 * C + c] = m * rH; g_nrm[5 * C + c] = rH;
        }
        __syncthreads();
        if (c < 2 * C) g_scr[4 * C + c] = 0.f;
    }
}

// edge sweep B (4 lanes/edge): v = H*relu(norm(y)); scatter into div; ACC += KEclose@v
__global__ void k_edgeB(const int* __restrict__ iInd, const int* __restrict__ jInd,
                        const float* __restrict__ KEclose, int layer) {
    __shared__ __align__(16) float sm[2 * C];
    __shared__ __align__(16) float KEc[CIN * C];
    int tx = threadIdx.x;
    if (tx < 2 * C) sm[tx] = g_nrm[tx];
    for (int idx = tx; idx < CIN * C; idx += 256) KEc[idx] = KEclose[idx];
    __syncthreads();
    int t = blockIdx.x * 256 + tx;
    int e = t >> 2;
    int s = t & 3;
    int i = __ldg(&iInd[e]);
    int j = __ldg(&jInd[e]);
    const float4* Zi = (const float4*)&g_Z[(size_t)i * C + s * 16];
    const float4* Zj = (const float4*)&g_Z[(size_t)j * C + s * 16];
    const float4* M4 = (const float4*)&sm[s * 16];
    const float4* R4 = (const float4*)&sm[C + s * 16];
    float4 v[4];
#pragma unroll
    for (int k = 0; k < 4; k++) {
        float4 a = __ldg(&Zi[k]), b = __ldg(&Zj[k]);
        float4 m = M4[k], r = R4[k];
        v[k].x = fmaxf((a.x - b.x) * r.x - m.x, 0.f);
        v[k].y = fmaxf((a.y - b.y) * r.y - m.y, 0.f);
        v[k].z = fmaxf((a.z - b.z) * r.z - m.z, 0.f);
        v[k].w = fmaxf((a.w - b.w) * r.w - m.w, 0.f);
    }
    float* dvi = &g_div[(size_t)i * C + s * 16];
    float* dvj = &g_div[(size_t)j * C + s * 16];
#pragma unroll
    for (int k = 0; k < 4; k++) red4(dvi + k * 4, v[k].x, v[k].y, v[k].z, v[k].w);
#pragma unroll
    for (int k = 0; k < 4; k++) red4(dvj + k * 4, -v[k].x, -v[k].y, -v[k].z, -v[k].w);
    float pr[16];
#pragma unroll
    for (int co = 0; co < 16; co++) {
        float acc = 0.f;
#pragma unroll
        for (int k = 0; k < 4; k++) {
            float4 w = *(const float4*)&KEc[co * C + s * 16 + k * 4];
            acc += w.x * v[k].x + w.y * v[k].y + w.z * v[k].z + w.w * v[k].w;
        }
        pr[co] = acc;
    }
#pragma unroll
    for (int d = 1; d < 4; d <<= 1) {
#pragma unroll
        for (int co = 0; co < 16; co++)
            pr[co] += __shfl_xor_sync(0xffffffffu, pr[co], d);
    }
    if (s == 0) {
        float4* A4 = (float4*)&g_ACC[(size_t)e * CIN];
        if (layer == 0) {
            A4[0] = make_float4(pr[0], pr[1], pr[2], pr[3]);
            A4[1] = make_float4(pr[4], pr[5], pr[6], pr[7]);
            A4[2] = make_float4(pr[8], pr[9], pr[10], pr[11]);
            A4[3] = make_float4(pr[12], pr[13], pr[14], pr[15]);
        } else {
            float4 t0 = A4[0], t1 = A4[1], t2 = A4[2], t3 = A4[3];
            t0.x += pr[0];  t0.y += pr[1];  t0.z += pr[2];  t0.w += pr[3];
            t1.x += pr[4];  t1.y += pr[5];  t1.z += pr[6];  t1.w += pr[7];
            t2.x += pr[8];  t2.y += pr[9];  t2.z += pr[10]; t2.w += pr[11];
            t3.x += pr[12]; t3.y += pr[13]; t3.z += pr[14]; t3.w += pr[15];
            A4[0] = t0; A4[1] = t1; A4[2] = t2; A4[3] = t3;
        }
    }
}

// xn -= relu(norm(U))*H + relu(norm(W))*H   (H folded)
__global__ void k_update() {
    __shared__ __align__(16) float sm[4 * C];
    int tx = threadIdx.x;
    sm[tx] = g_nrm[2 * C + tx];
    __syncthreads();
    int n = blockIdx.x * blockDim.x + tx;
    if (n >= NN) return;
#pragma unroll
    for (int q = 0; q < 16; q++) {
        float4 u = *(const float4*)&g_U[(size_t)n * C + q * 4];
        float4 w = *(const float4*)&g_W[(size_t)n * C + q * 4];
        float4 x = *(float4*)&g_Xn[(size_t)n * C + q * 4];
        float4 mw = *(const float4*)&sm[q * 4];
        float4 rw = *(const float4*)&sm[C + q * 4];
        float4 mu = *(const float4*)&sm[2 * C + q * 4];
        float4 ru = *(const float4*)&sm[3 * C + q * 4];
        x.x -= fmaxf(u.x * ru.x - mu.x, 0.f) + fmaxf(w.x * rw.x - mw.x, 0.f);
        x.y -= fmaxf(u.y * ru.y - mu.y, 0.f) + fmaxf(w.y * rw.y - mw.y, 0.f);
        x.z -= fmaxf(u.z * ru.z - mu.z, 0.f) + fmaxf(w.z * rw.z - mw.z, 0.f);
        x.w -= fmaxf(u.w * ru.w - mu.w, 0.f) + fmaxf(w.w * rw.w - mw.w, 0.f);
        *(float4*)&g_Xn[(size_t)n * C + q * 4] = x;
    }
}

// node close: out[co*count + n] = sum_k Kc[co*C+k] * In[n][k]
__global__ void k_close(const float* __restrict__ Kc, const float* __restrict__ In,
                        float* __restrict__ out, int count) {
    __shared__ __align__(16) float Ks[CIN * C];
    for (int idx = threadIdx.x; idx < CIN * C; idx += blockDim.x) Ks[idx] = Kc[idx];
    __syncthreads();
    int n = blockIdx.x * blockDim.x + threadIdx.x;
    if (n >= count) return;
    float4 row[16];
#pragma unroll
    for (int q = 0; q < 16; q++)
        row[q] = __ldg((const float4*)&In[(size_t)n * C + q * 4]);
#pragma unroll
    for (int co = 0; co < CIN; co++) {
        float acc = 0.f;
#pragma unroll
        for (int q = 0; q < 16; q++) {
            float4 w = *(const float4*)&Ks[co * C + q * 4];
            acc += w.x * row[q].x + w.y * row[q].y + w.z * row[q].z + w.w * row[q].w;
        }
        out[(size_t)co * count + n] = acc;
    }
}

// edge close: out[co][e] = M2 @ xe_raw + ACC[e][co]
__global__ void k_closeE(const float* __restrict__ xe, float* __restrict__ out) {
    __shared__ float M2s[CIN * CIN];
    if (threadIdx.x < CIN * CIN) M2s[threadIdx.x] = g_M2[threadIdx.x];
    __syncthreads();
    int e = blockIdx.x * blockDim.x + threadIdx.x;
    if (e >= NE) return;
    float xr[CIN];
#pragma unroll
    for (int c = 0; c < CIN; c++) xr[c] = __ldg(&xe[(size_t)c * NE + e]);
    float a[CIN];
    const float4* A4 = (const float4*)&g_ACC[(size_t)e * CIN];
    ((float4*)a)[0] = A4[0]; ((float4*)a)[1] = A4[1];
    ((float4*)a)[2] = A4[2]; ((float4*)a)[3] = A4[3];
#pragma unroll
    for (int co = 0; co < CIN; co++) {
        float s = a[co];
#pragma unroll
        for (int c = 0; c < CIN; c++) s += M2s[co * CIN + c] * xr[c];
        out[(size_t)co * NE + e] = s;
    }
}

extern "C" void kernel_launch(void* const* d_in, const int* in_sizes, int n_in,
                              void* d_out, int out_size) {
    const float* xn      = (const float*)d_in[0];
    const float* xe      = (const float*)d_in[1];
    const int*   iInd    = (const int*)d_in[2];
    const int*   jInd    = (const int*)d_in[3];
    const float* KNopen  = (const float*)d_in[4];
    const float* KEopen  = (const float*)d_in[5];
    const float* KNclose = (const float*)d_in[6];
    const float* KEclose = (const float*)d_in[7];
    const float* KN      = (const float*)d_in[8];
    const float* KE      = (const float*)d_in[9];
    const float* KD      = (const float*)d_in[10];
    float* out = (float*)d_out;
    (void)in_sizes; (void)n_in; (void)out_size;

    float *pXn, *pZ, *pW, *pU, *pDiv, *pDiv16;
    cudaGetSymbolAddress((void**)&pXn, g_Xn);
    cudaGetSymbolAddress((void**)&pZ, g_Z);
    cudaGetSymbolAddress((void**)&pW, g_W);
    cudaGetSymbolAddress((void**)&pU, g_U);
    cudaGetSymbolAddress((void**)&pDiv, g_div);
    cudaGetSymbolAddress((void**)&pDiv16, g_div16);

    const int TB = 256;
    const int gN = (NN + TB - 1) / TB;            // 196
    const int gE = (NE + TB - 1) / TB;            // 3125
    const int gMM = (NN + 63) / 64;               // 782
    const int gEB = (NE * 4) / TB;                // 12500

    k_init<<<gE, TB>>>();
    k_m2<<<1, TB>>>(KEclose, KEopen);
    k_open<<<gN, TB>>>(xn, KNopen, pXn, NN);
    k_edge0<<<gE, TB>>>(xe, iInd, jInd);
    // expand: g_div = KEopen @ g_div16
    k_mm4q<CIN><<<gMM, TB>>>(pDiv16, KEopen, pDiv, NN, -1);

    for (int l = 0; l < NL; l++) {
        const float* Kn = KN + (size_t)l * C * C;
        const float* Ke = KE + (size_t)l * C * C;
        const float* Kd = KD + (size_t)l * C * C;

        k_mm4q<C><<<gMM, TB>>>(pXn, Kn, pZ, NN, -1);
        k_mm4q<C><<<gMM, TB>>>(pXn, Kd, pW, NN, 2 * C);
        k_edgeA<<<2048, TB>>>(iInd, jInd);
        k_scales<<<1, TB>>>(0);
        k_edgeB<<<gEB, TB>>>(iInd, jInd, KEclose, l);
        k_mm4q<C><<<gMM, TB>>>(pDiv, Ke, pU, NN, 4 * C);
        k_scales<<<1, TB>>>(1);
        k_update<<<gN, TB>>>();
    }

    k_close<<<gN, TB>>>(KNclose, pXn, out, NN);
    k_closeE<<<gE, TB>>>(xe, out + (size_t)CIN * NN);
}

// round 6
// speedup vs baseline: 1.2945x; 1.2945x over previous
#include <cuda_runtime.h>

#define NN 50000
#define NE 800000
#define C 64
#define CIN 16
#define NL 4
#define HSTEP 0.1f
#define EPSV 1e-3f

// ---- static device scratch (no allocs allowed) ----
__device__ __align__(256) float g_Xn[NN * C];          // 12.8 MB
__device__ __align__(256) float g_Xe[(size_t)NE * C];  // 204.8 MB
__device__ __align__(256) float g_Z[NN * C];
__device__ __align__(256) float g_W[NN * C];
__device__ __align__(256) float g_U[NN * C];
__device__ __align__(256) float g_div[NN * C];
__device__ __align__(256) float g_scr[6 * C];  // sA qA sW qW sU qU
__device__ __align__(256) float g_nrm[6 * C];  // mA rA mW rW mU rU

__device__ __forceinline__ void red4(float* p, float x, float y, float z, float w) {
    asm volatile("red.global.add.v4.f32 [%0], {%1,%2,%3,%4};"
                 :: "l"(p), "f"(x), "f"(y), "f"(z), "f"(w) : "memory");
}

// zero div + scratch
__global__ void k_zero() {
    int stride = gridDim.x * blockDim.x;
    int t0 = blockIdx.x * blockDim.x + threadIdx.x;
    for (int i = t0; i < NN * C; i += stride) g_div[i] = 0.f;
    if (t0 < 6 * C) g_scr[t0] = 0.f;
}

// out[item][k] = sum_c K[k*CIN+c] * in[c*count+item]   (K is [C x CIN])
__global__ void k_open(const float* __restrict__ in, const float* __restrict__ K,
                       float* __restrict__ out, int count) {
    __shared__ __align__(16) float KT[CIN * C];  // KT[c*C + k]
    for (int idx = threadIdx.x; idx < CIN * C; idx += blockDim.x) {
        int k = idx & (C - 1); int c = idx >> 6;
        KT[idx] = K[k * CIN + c];
    }
    __syncthreads();
    int n = blockIdx.x * blockDim.x + threadIdx.x;
    if (n >= count) return;
    float4 acc[C / 4];
#pragma unroll
    for (int q = 0; q < C / 4; q++) acc[q] = make_float4(0.f, 0.f, 0.f, 0.f);
#pragma unroll
    for (int c = 0; c < CIN; c++) {
        float v = __ldg(&in[(size_t)c * count + n]);
        const float4* w = (const float4*)&KT[c * C];
#pragma unroll
        for (int q = 0; q < C / 4; q++) {
            float4 t = w[q];
            acc[q].x += t.x * v; acc[q].y += t.y * v;
            acc[q].z += t.z * v; acc[q].w += t.w * v;
        }
    }
    float4* o = (float4*)&out[(size_t)n * C];
#pragma unroll
    for (int q = 0; q < C / 4; q++) o[q] = acc[q];
}

// Out[n][k] = sum_c M[k*C+c] * In[n][c].  4 threads per node, 16 outputs each.
// Weights transposed in smem; input rows read direct from global (quad-broadcast).
__global__ void k_mmv2(const float* __restrict__ In, const float* __restrict__ M,
                       float* __restrict__ Out, int count) {
    __shared__ __align__(16) float MT[C * C];  // MT[c*C + k]
    for (int idx = threadIdx.x; idx < C * C; idx += 256) {
        int k = idx & (C - 1); int c = idx >> 6;
        MT[idx] = M[k * C + c];
    }
    __syncthreads();
    int t = blockIdx.x * 256 + threadIdx.x;
    int n = t >> 2;
    int q = t & 3;
    if (n >= count) return;
    const float4* row = (const float4*)&In[(size_t)n * C];
    float4 a0 = make_float4(0.f, 0.f, 0.f, 0.f), a1 = a0, a2 = a0, a3 = a0;
#pragma unroll
    for (int c4 = 0; c4 < 16; c4++) {
        float4 v = __ldg(&row[c4]);
#pragma unroll
        for (int cc = 0; cc < 4; cc++) {
            float s = (cc == 0) ? v.x : (cc == 1) ? v.y : (cc == 2) ? v.z : v.w;
            const float4* w = (const float4*)&MT[(c4 * 4 + cc) * C + q * 16];
            float4 w0 = w[0], w1 = w[1], w2 = w[2], w3 = w[3];
            a0.x += w0.x * s; a0.y += w0.y * s; a0.z += w0.z * s; a0.w += w0.w * s;
            a1.x += w1.x * s; a1.y += w1.y * s; a1.z += w1.z * s; a1.w += w1.w * s;
            a2.x += w2.x * s; a2.y += w2.y * s; a2.z += w2.z * s; a2.w += w2.w * s;
            a3.x += w3.x * s; a3.y += w3.y * s; a3.z += w3.z * s; a3.w += w3.w * s;
        }
    }
    float4* o = (float4*)&Out[(size_t)n * C + q * 16];
    o[0] = a0; o[1] = a1; o[2] = a2; o[3] = a3;
}

// per-channel sum & sumsq of X[count][64] into g_scr[off .. off+127]
__global__ void k_stats(const float* __restrict__ X, int count, int off) {
    int t = blockIdx.x * blockDim.x + threadIdx.x;
    int c = t & (C - 1);
    int row0 = t >> 6;
    int nrows = (gridDim.x * blockDim.x) >> 6;
    float s = 0.f, q = 0.f;
    for (int n = row0; n < count; n += nrows) {
        float v = __ldg(&X[(size_t)n * C + c]);
        s += v; q += v * v;
    }
    __shared__ float ss[C], sq[C];
    if (threadIdx.x < C) { ss[threadIdx.x] = 0.f; sq[threadIdx.x] = 0.f; }
    __syncthreads();
    atomicAdd(&ss[c], s);
    atomicAdd(&sq[c], q);
    __syncthreads();
    if (threadIdx.x < C) {
        atomicAdd(&g_scr[off + threadIdx.x], ss[threadIdx.x]);
        atomicAdd(&g_scr[off + C + threadIdx.x], sq[threadIdx.x]);
    }
}

// edge sweep A: per-channel sum/sumsq of y = Z[:,i]-Z[:,j]  (16 lanes per edge)
__global__ void k_edgeA(const int* __restrict__ iInd, const int* __restrict__ jInd) {
    int t = blockIdx.x * blockDim.x + threadIdx.x;
    int lane = t & 15;
    int grp = t >> 4;
    int ngrp = (gridDim.x * blockDim.x) >> 4;
    float4 s = make_float4(0.f, 0.f, 0.f, 0.f);
    float4 q = make_float4(0.f, 0.f, 0.f, 0.f);
    for (int e = grp; e < NE; e += ngrp) {
        int i = __ldg(&iInd[e]);
        int j = __ldg(&jInd[e]);
        float4 a = __ldg((const float4*)&g_Z[(size_t)i * C + lane * 4]);
        float4 b = __ldg((const float4*)&g_Z[(size_t)j * C + lane * 4]);
        float yx = a.x - b.x, yy = a.y - b.y, yz = a.z - b.z, yw = a.w - b.w;
        s.x += yx; s.y += yy; s.z += yz; s.w += yw;
        q.x += yx * yx; q.y += yy * yy; q.z += yz * yz; q.w += yw * yw;
    }
    __shared__ float ss[C], sq[C];
    if (threadIdx.x < C) { ss[threadIdx.x] = 0.f; sq[threadIdx.x] = 0.f; }
    __syncthreads();
    int ch = lane * 4;
    atomicAdd(&ss[ch + 0], s.x); atomicAdd(&ss[ch + 1], s.y);
    atomicAdd(&ss[ch + 2], s.z); atomicAdd(&ss[ch + 3], s.w);
    atomicAdd(&sq[ch + 0], q.x); atomicAdd(&sq[ch + 1], q.y);
    atomicAdd(&sq[ch + 2], q.z); atomicAdd(&sq[ch + 3], q.w);
    __syncthreads();
    if (threadIdx.x < C) {
        atomicAdd(&g_scr[threadIdx.x], ss[threadIdx.x]);
        atomicAdd(&g_scr[C + threadIdx.x], sq[threadIdx.x]);
    }
}

// compute mean / 1/sqrt(sumsq_centered + eps)
__global__ void k_scales(int which) {
    int c = threadIdx.x;
    if (c >= C) return;
    if (which == 0) {
        float s = g_scr[c], q = g_scr[C + c];
        float m = s / (float)NE;
        g_nrm[c] = m;
        g_nrm[C + c] = 1.f / sqrtf(fmaxf(q - s * m, 0.f) + EPSV);
        s = g_scr[2 * C + c]; q = g_scr[3 * C + c];
        m = s / (float)NN;
        g_nrm[2 * C + c] = m;
        g_nrm[3 * C + c] = 1.f / sqrtf(fmaxf(q - s * m, 0.f) + EPSV);
    } else {
        float s = g_scr[4 * C + c], q = g_scr[5 * C + c];
        float m = s / (float)NN;
        g_nrm[4 * C + c] = m;
        g_nrm[5 * C + c] = 1.f / sqrtf(fmaxf(q - s * m, 0.f) + EPSV);
    }
}

// edge sweep B: xe += H*relu((y-m)*r); scatter +/- xe into div
__global__ void k_edgeB(const int* __restrict__ iInd, const int* __restrict__ jInd) {
    __shared__ __align__(16) float sm[2 * C];
    if (threadIdx.x < C) {
        sm[threadIdx.x] = g_nrm[threadIdx.x];
        sm[C + threadIdx.x] = g_nrm[C + threadIdx.x];
    }
    __syncthreads();
    int t = blockIdx.x * blockDim.x + threadIdx.x;
    int e = t >> 4;
    if (e >= NE) return;
    int lane = t & 15;
    int i = __ldg(&iInd[e]);
    int j = __ldg(&jInd[e]);
    float4 a = __ldg((const float4*)&g_Z[(size_t)i * C + lane * 4]);
    float4 b = __ldg((const float4*)&g_Z[(size_t)j * C + lane * 4]);
    float4 m = *(const float4*)&sm[lane * 4];
    float4 r = *(const float4*)&sm[C + lane * 4];
    float4 xe = *(const float4*)&g_Xe[(size_t)e * C + lane * 4];
    xe.x += HSTEP * fmaxf((a.x - b.x - m.x) * r.x, 0.f);
    xe.y += HSTEP * fmaxf((a.y - b.y - m.y) * r.y, 0.f);
    xe.z += HSTEP * fmaxf((a.z - b.z - m.z) * r.z, 0.f);
    xe.w += HSTEP * fmaxf((a.w - b.w - m.w) * r.w, 0.f);
    *(float4*)&g_Xe[(size_t)e * C + lane * 4] = xe;
    red4(&g_div[(size_t)i * C + lane * 4], xe.x, xe.y, xe.z, xe.w);
    red4(&g_div[(size_t)j * C + lane * 4], -xe.x, -xe.y, -xe.z, -xe.w);
}

// xn -= H * (relu(norm(U)) + relu(norm(W)))
__global__ void k_update() {
    __shared__ __align__(16) float sm[4 * C];  // mW rW mU rU
    if (threadIdx.x < C) {
        sm[threadIdx.x]         = g_nrm[2 * C + threadIdx.x];
        sm[C + threadIdx.x]     = g_nrm[3 * C + threadIdx.x];
        sm[2 * C + threadIdx.x] = g_nrm[4 * C + threadIdx.x];
        sm[3 * C + threadIdx.x] = g_nrm[5 * C + threadIdx.x];
    }
    __syncthreads();
    int n = blockIdx.x * blockDim.x + threadIdx.x;
    if (n >= NN) return;
#pragma unroll
    for (int q = 0; q < 16; q++) {
        float4 u = *(const float4*)&g_U[(size_t)n * C + q * 4];
        float4 w = *(const float4*)&g_W[(size_t)n * C + q * 4];
        float4 x = *(float4*)&g_Xn[(size_t)n * C + q * 4];
        float4 mw = *(const float4*)&sm[q * 4];
        float4 rw = *(const float4*)&sm[C + q * 4];
        float4 mu = *(const float4*)&sm[2 * C + q * 4];
        float4 ru = *(const float4*)&sm[3 * C + q * 4];
        x.x -= HSTEP * (fmaxf((u.x - mu.x) * ru.x, 0.f) + fmaxf((w.x - mw.x) * rw.x, 0.f));
        x.y -= HSTEP * (fmaxf((u.y - mu.y) * ru.y, 0.f) + fmaxf((w.y - mw.y) * rw.y, 0.f));
        x.z -= HSTEP * (fmaxf((u.z - mu.z) * ru.z, 0.f) + fmaxf((w.z - mw.z) * rw.z, 0.f));
        x.w -= HSTEP * (fmaxf((u.w - mu.w) * ru.w, 0.f) + fmaxf((w.w - mw.w) * rw.w, 0.f));
        *(float4*)&g_Xn[(size_t)n * C + q * 4] = x;
    }
}

// out[co*count + n] = sum_k Kc[co*C+k] * In[n][k]   (Kc is [16 x 64])
__global__ void k_close(const float* __restrict__ Kc, const float* __restrict__ In,
                        float* __restrict__ out, int count) {
    __shared__ __align__(16) float Ks[CIN * C];
    for (int idx = threadIdx.x; idx < CIN * C; idx += blockDim.x) Ks[idx] = Kc[idx];
    __syncthreads();
    int n = blockIdx.x * blockDim.x + threadIdx.x;
    if (n >= count) return;
    float4 row[16];
#pragma unroll
    for (int q = 0; q < 16; q++)
        row[q] = __ldg((const float4*)&In[(size_t)n * C + q * 4]);
#pragma unroll
    for (int co = 0; co < CIN; co++) {
        float acc = 0.f;
#pragma unroll
        for (int q = 0; q < 16; q++) {
            float4 w = *(const float4*)&Ks[co * C + q * 4];
            acc += w.x * row[q].x + w.y * row[q].y + w.z * row[q].z + w.w * row[q].w;
        }
        out[(size_t)co * count + n] = acc;
    }
}

extern "C" void kernel_launch(void* const* d_in, const int* in_sizes, int n_in,
                              void* d_out, int out_size) {
    const float* xn      = (const float*)d_in[0];
    const float* xe      = (const float*)d_in[1];
    const int*   iInd    = (const int*)d_in[2];
    const int*   jInd    = (const int*)d_in[3];
    const float* KNopen  = (const float*)d_in[4];
    const float* KEopen  = (const float*)d_in[5];
    const float* KNclose = (const float*)d_in[6];
    const float* KEclose = (const float*)d_in[7];
    const float* KN      = (const float*)d_in[8];
    const float* KE      = (const float*)d_in[9];
    const float* KD      = (const float*)d_in[10];
    float* out = (float*)d_out;
    (void)in_sizes; (void)n_in; (void)out_size;

    float *pXn, *pXe, *pZ, *pW, *pU, *pDiv;
    cudaGetSymbolAddress((void**)&pXn, g_Xn);
    cudaGetSymbolAddress((void**)&pXe, g_Xe);
    cudaGetSymbolAddress((void**)&pZ, g_Z);
    cudaGetSymbolAddress((void**)&pW, g_W);
    cudaGetSymbolAddress((void**)&pU, g_U);
    cudaGetSymbolAddress((void**)&pDiv, g_div);

    const int TB = 256;
    const int gN = (NN + TB - 1) / TB;             // 196
    const int gE = (NE + TB - 1) / TB;             // 3125
    const int gMM = (NN * 4 + TB - 1) / TB;        // 782
    const int gEB = ((NE * 16) + TB - 1) / TB;     // 50000

    k_open<<<gN, TB>>>(xn, KNopen, pXn, NN);
    k_open<<<gE, TB>>>(xe, KEopen, pXe, NE);

    for (int l = 0; l < NL; l++) {
        const float* Kn = KN + (size_t)l * C * C;
        const float* Ke = KE + (size_t)l * C * C;
        const float* Kd = KD + (size_t)l * C * C;

        k_zero<<<256, TB>>>();
        k_mmv2<<<gMM, TB>>>(pXn, Kn, pZ, NN);
        k_mmv2<<<gMM, TB>>>(pXn, Kd, pW, NN);
        k_stats<<<256, TB>>>(pW, NN, 2 * C);
        k_edgeA<<<2048, TB>>>(iInd, jInd);
        k_scales<<<1, 64>>>(0);
        k_edgeB<<<gEB, TB>>>(iInd, jInd);
        k_mmv2<<<gMM, TB>>>(pDiv, Ke, pU, NN);
        k_stats<<<256, TB>>>(pU, NN, 4 * C);
        k_scales<<<1, 64>>>(1);
        k_update<<<gN, TB>>>();
    }

    k_close<<<gN, TB>>>(KNclose, pXn, out, NN);
    k_close<<<gE, TB>>>(KEclose, pXe, out + (size_t)CIN * NN, NE);
}

// round 8
// speedup vs baseline: 1.7972x; 1.3883x over previous
#include <cuda_runtime.h>

#define NN 50000
#define NE 800000
#define C 64
#define CIN 16
#define NL 4
#define HSTEP 0.1f
#define EPSV 1e-3f

// ---- static device scratch (no allocs allowed) ----
__device__ __align__(256) float g_Xn[NN * C];          // 12.8 MB
__device__ __align__(256) float g_Xe[(size_t)NE * C];  // 204.8 MB
__device__ __align__(256) float g_Z[NN * C];
__device__ __align__(256) float g_W[NN * C];
__device__ __align__(256) float g_U[NN * C];
__device__ __align__(256) float g_div[NN * C];
__device__ __align__(256) float g_scr[6 * C];  // sA qA sW qW sU qU
__device__ __align__(256) float g_nrm[6 * C];  // mA rA mW rW mU rU

__device__ __forceinline__ void red4(float* p, float x, float y, float z, float w) {
    asm volatile("red.global.add.v4.f32 [%0], {%1,%2,%3,%4};"
                 :: "l"(p), "f"(x), "f"(y), "f"(z), "f"(w) : "memory");
}

// zero div + scratch
__global__ void k_zero() {
    int stride = gridDim.x * blockDim.x;
    int t0 = blockIdx.x * blockDim.x + threadIdx.x;
    for (int i = t0; i < NN * C; i += stride) g_div[i] = 0.f;
    if (t0 < 6 * C) g_scr[t0] = 0.f;
}

// out[item][k] = sum_c K[k*CIN+c] * in[c*count+item]   (K is [C x CIN])
__global__ void k_open(const float* __restrict__ in, const float* __restrict__ K,
                       float* __restrict__ out, int count) {
    __shared__ __align__(16) float KT[CIN * C];  // KT[c*C + k]
    for (int idx = threadIdx.x; idx < CIN * C; idx += blockDim.x) {
        int k = idx & (C - 1); int c = idx >> 6;
        KT[idx] = K[k * CIN + c];
    }
    __syncthreads();
    int n = blockIdx.x * blockDim.x + threadIdx.x;
    if (n >= count) return;
    float4 acc[C / 4];
#pragma unroll
    for (int q = 0; q < C / 4; q++) acc[q] = make_float4(0.f, 0.f, 0.f, 0.f);
#pragma unroll
    for (int c = 0; c < CIN; c++) {
        float v = __ldg(&in[(size_t)c * count + n]);
        const float4* w = (const float4*)&KT[c * C];
#pragma unroll
        for (int q = 0; q < C / 4; q++) {
            float4 t = w[q];
            acc[q].x += t.x * v; acc[q].y += t.y * v;
            acc[q].z += t.z * v; acc[q].w += t.w * v;
        }
    }
    float4* o = (float4*)&out[(size_t)n * C];
#pragma unroll
    for (int q = 0; q < C / 4; q++) o[q] = acc[q];
}

// Out[n][k] = sum_c M[k*C+c] * In[n][c].
// 2 nodes x 16 outputs per thread; weights in smem with padded conflict-free
// quad layout: MT[c*80 + q*20 + f] = M[(q*16+f)*C + c].
// Bank groups per q: q*20 mod 32 = {0,20,8,28} -> disjoint. Row stride 80f.
__global__ void k_mmv3(const float* __restrict__ In, const float* __restrict__ M,
                       float* __restrict__ Out, int count) {
    __shared__ __align__(16) float MT[C * 80];  // 20 KB
    for (int idx = threadIdx.x; idx < C * C; idx += 256) {
        int k = idx & (C - 1); int c = idx >> 6;
        MT[c * 80 + (k >> 4) * 20 + (k & 15)] = M[k * C + c];
    }
    __syncthreads();
    int t = blockIdx.x * 256 + threadIdx.x;
    int p = t >> 2;        // node pair
    int q = t & 3;         // output quad (16 outputs)
    int n0 = p * 2;
    if (n0 >= count) return;
    const float4* r0 = (const float4*)&In[(size_t)n0 * C];
    const float4* r1 = (const float4*)&In[(size_t)(n0 + 1) * C];
    float4 b0 = make_float4(0.f, 0.f, 0.f, 0.f), b1 = b0, b2 = b0, b3 = b0;
    float4 d0 = b0, d1 = b0, d2 = b0, d3 = b0;
#pragma unroll
    for (int c4 = 0; c4 < 16; c4++) {
        float4 u = __ldg(&r0[c4]);
        float4 v = __ldg(&r1[c4]);
#pragma unroll
        for (int cc = 0; cc < 4; cc++) {
            float su = (cc == 0) ? u.x : (cc == 1) ? u.y : (cc == 2) ? u.z : u.w;
            float sv = (cc == 0) ? v.x : (cc == 1) ? v.y : (cc == 2) ? v.z : v.w;
            const float4* w = (const float4*)&MT[(c4 * 4 + cc) * 80 + q * 20];
            float4 w0 = w[0], w1 = w[1], w2 = w[2], w3 = w[3];
            b0.x += w0.x * su; b0.y += w0.y * su; b0.z += w0.z * su; b0.w += w0.w * su;
            b1.x += w1.x * su; b1.y += w1.y * su; b1.z += w1.z * su; b1.w += w1.w * su;
            b2.x += w2.x * su; b2.y += w2.y * su; b2.z += w2.z * su; b2.w += w2.w * su;
            b3.x += w3.x * su; b3.y += w3.y * su; b3.z += w3.z * su; b3.w += w3.w * su;
            d0.x += w0.x * sv; d0.y += w0.y * sv; d0.z += w0.z * sv; d0.w += w0.w * sv;
            d1.x += w1.x * sv; d1.y += w1.y * sv; d1.z += w1.z * sv; d1.w += w1.w * sv;
            d2.x += w2.x * sv; d2.y += w2.y * sv; d2.z += w2.z * sv; d2.w += w2.w * sv;
            d3.x += w3.x * sv; d3.y += w3.y * sv; d3.z += w3.z * sv; d3.w += w3.w * sv;
        }
    }
    float4* o0 = (float4*)&Out[(size_t)n0 * C + q * 16];
    o0[0] = b0; o0[1] = b1; o0[2] = b2; o0[3] = b3;
    float4* o1 = (float4*)&Out[(size_t)(n0 + 1) * C + q * 16];
    o1[0] = d0; o1[1] = d1; o1[2] = d2; o1[3] = d3;
}

// per-channel sum & sumsq of X[count][64] into g_scr[off .. off+127]
__global__ void k_stats(const float* __restrict__ X, int count, int off) {
    int t = blockIdx.x * blockDim.x + threadIdx.x;
    int c = t & (C - 1);
    int row0 = t >> 6;
    int nrows = (gridDim.x * blockDim.x) >> 6;
    float s = 0.f, q = 0.f;
    for (int n = row0; n < count; n += nrows) {
        float v = __ldg(&X[(size_t)n * C + c]);
        s += v; q += v * v;
    }
    __shared__ float ss[C], sq[C];
    if (threadIdx.x < C) { ss[threadIdx.x] = 0.f; sq[threadIdx.x] = 0.f; }
    __syncthreads();
    atomicAdd(&ss[c], s);
    atomicAdd(&sq[c], q);
    __syncthreads();
    if (threadIdx.x < C) {
        atomicAdd(&g_scr[off + threadIdx.x], ss[threadIdx.x]);
        atomicAdd(&g_scr[off + C + threadIdx.x], sq[threadIdx.x]);
    }
}

// edge sweep A: per-channel sum/sumsq of y = Z[:,i]-Z[:,j]  (16 lanes per edge)
__global__ void k_edgeA(const int* __restrict__ iInd, const int* __restrict__ jInd) {
    int t = blockIdx.x * blockDim.x + threadIdx.x;
    int lane = t & 15;
    int grp = t >> 4;
    int ngrp = (gridDim.x * blockDim.x) >> 4;
    float4 s = make_float4(0.f, 0.f, 0.f, 0.f);
    float4 q = make_float4(0.f, 0.f, 0.f, 0.f);
    for (int e = grp; e < NE; e += ngrp) {
        int i = __ldg(&iInd[e]);
        int j = __ldg(&jInd[e]);
        float4 a = __ldg((const float4*)&g_Z[(size_t)i * C + lane * 4]);
        float4 b = __ldg((const float4*)&g_Z[(size_t)j * C + lane * 4]);
        float yx = a.x - b.x, yy = a.y - b.y, yz = a.z - b.z, yw = a.w - b.w;
        s.x += yx; s.y += yy; s.z += yz; s.w += yw;
        q.x += yx * yx; q.y += yy * yy; q.z += yz * yz; q.w += yw * yw;
    }
    __shared__ float ss[C], sq[C];
    if (threadIdx.x < C) { ss[threadIdx.x] = 0.f; sq[threadIdx.x] = 0.f; }
    __syncthreads();
    int ch = lane * 4;
    atomicAdd(&ss[ch + 0], s.x); atomicAdd(&ss[ch + 1], s.y);
    atomicAdd(&ss[ch + 2], s.z); atomicAdd(&ss[ch + 3], s.w);
    atomicAdd(&sq[ch + 0], q.x); atomicAdd(&sq[ch + 1], q.y);
    atomicAdd(&sq[ch + 2], q.z); atomicAdd(&sq[ch + 3], q.w);
    __syncthreads();
    if (threadIdx.x < C) {
        atomicAdd(&g_scr[threadIdx.x], ss[threadIdx.x]);
        atomicAdd(&g_scr[C + threadIdx.x], sq[threadIdx.x]);
    }
}

// compute mean / 1/sqrt(sumsq_centered + eps)
__global__ void k_scales(int which) {
    int c = threadIdx.x;
    if (c >= C) return;
    if (which == 0) {
        float s = g_scr[c], q = g_scr[C + c];
        float m = s / (float)NE;
        g_nrm[c] = m;
        g_nrm[C + c] = 1.f / sqrtf(fmaxf(q - s * m, 0.f) + EPSV);
        s = g_scr[2 * C + c]; q = g_scr[3 * C + c];
        m = s / (float)NN;
        g_nrm[2 * C + c] = m;
        g_nrm[3 * C + c] = 1.f / sqrtf(fmaxf(q - s * m, 0.f) + EPSV);
    } else {
        float s = g_scr[4 * C + c], q = g_scr[5 * C + c];
        float m = s / (float)NN;
        g_nrm[4 * C + c] = m;
        g_nrm[5 * C + c] = 1.f / sqrtf(fmaxf(q - s * m, 0.f) + EPSV);
    }
}

// edge sweep B: xe += H*relu((y-m)*r); scatter +/- xe into div
__global__ void k_edgeB(const int* __restrict__ iInd, const int* __restrict__ jInd) {
    __shared__ __align__(16) float sm[2 * C];
    if (threadIdx.x < C) {
        sm[threadIdx.x] = g_nrm[threadIdx.x];
        sm[C + threadIdx.x] = g_nrm[C + threadIdx.x];
    }
    __syncthreads();
    int t = blockIdx.x * blockDim.x + threadIdx.x;
    int e = t >> 4;
    if (e >= NE) return;
    int lane = t & 15;
    int i = __ldg(&iInd[e]);
    int j = __ldg(&jInd[e]);
    float4 a = __ldg((const float4*)&g_Z[(size_t)i * C + lane * 4]);
    float4 b = __ldg((const float4*)&g_Z[(size_t)j * C + lane * 4]);
    float4 m = *(const float4*)&sm[lane * 4];
    float4 r = *(const float4*)&sm[C + lane * 4];
    float4 xe = *(const float4*)&g_Xe[(size_t)e * C + lane * 4];
    xe.x += HSTEP * fmaxf((a.x - b.x - m.x) * r.x, 0.f);
    xe.y += HSTEP * fmaxf((a.y - b.y - m.y) * r.y, 0.f);
    xe.z += HSTEP * fmaxf((a.z - b.z - m.z) * r.z, 0.f);
    xe.w += HSTEP * fmaxf((a.w - b.w - m.w) * r.w, 0.f);
    *(float4*)&g_Xe[(size_t)e * C + lane * 4] = xe;
    red4(&g_div[(size_t)i * C + lane * 4], xe.x, xe.y, xe.z, xe.w);
    red4(&g_div[(size_t)j * C + lane * 4], -xe.x, -xe.y, -xe.z, -xe.w);
}

// xn -= H * (relu(norm(U)) + relu(norm(W)))
__global__ void k_update() {
    __shared__ __align__(16) float sm[4 * C];  // mW rW mU rU
    if (threadIdx.x < C) {
        sm[threadIdx.x]         = g_nrm[2 * C + threadIdx.x];
        sm[C + threadIdx.x]     = g_nrm[3 * C + threadIdx.x];
        sm[2 * C + threadIdx.x] = g_nrm[4 * C + threadIdx.x];
        sm[3 * C + threadIdx.x] = g_nrm[5 * C + threadIdx.x];
    }
    __syncthreads();
    int n = blockIdx.x * blockDim.x + threadIdx.x;
    if (n >= NN) return;
#pragma unroll
    for (int q = 0; q < 16; q++) {
        float4 u = *(const float4*)&g_U[(size_t)n * C + q * 4];
        float4 w = *(const float4*)&g_W[(size_t)n * C + q * 4];
        float4 x = *(float4*)&g_Xn[(size_t)n * C + q * 4];
        float4 mw = *(const float4*)&sm[q * 4];
        float4 rw = *(const float4*)&sm[C + q * 4];
        float4 mu = *(const float4*)&sm[2 * C + q * 4];
        float4 ru = *(const float4*)&sm[3 * C + q * 4];
        x.x -= HSTEP * (fmaxf((u.x - mu.x) * ru.x, 0.f) + fmaxf((w.x - mw.x) * rw.x, 0.f));
        x.y -= HSTEP * (fmaxf((u.y - mu.y) * ru.y, 0.f) + fmaxf((w.y - mw.y) * rw.y, 0.f));
        x.z -= HSTEP * (fmaxf((u.z - mu.z) * ru.z, 0.f) + fmaxf((w.z - mw.z) * rw.z, 0.f));
        x.w -= HSTEP * (fmaxf((u.w - mu.w) * ru.w, 0.f) + fmaxf((w.w - mw.w) * rw.w, 0.f));
        *(float4*)&g_Xn[(size_t)n * C + q * 4] = x;
    }
}

// out[co*count + n] = sum_k Kc[co*C+k] * In[n][k]   (Kc is [16 x 64])
__global__ void k_close(const float* __restrict__ Kc, const float* __restrict__ In,
                        float* __restrict__ out, int count) {
    __shared__ __align__(16) float Ks[CIN * C];
    for (int idx = threadIdx.x; idx < CIN * C; idx += blockDim.x) Ks[idx] = Kc[idx];
    __syncthreads();
    int n = blockIdx.x * blockDim.x + threadIdx.x;
    if (n >= count) return;
    float4 row[16];
#pragma unroll
    for (int q = 0; q < 16; q++)
        row[q] = __ldg((const float4*)&In[(size_t)n * C + q * 4]);
#pragma unroll
    for (int co = 0; co < CIN; co++) {
        float acc = 0.f;
#pragma unroll
        for (int q = 0; q < 16; q++) {
            float4 w = *(const float4*)&Ks[co * C + q * 4];
            acc += w.x * row[q].x + w.y * row[q].y + w.z * row[q].z + w.w * row[q].w;
        }
        out[(size_t)co * count + n] = acc;
    }
}

extern "C" void kernel_launch(void* const* d_in, const int* in_sizes, int n_in,
                              void* d_out, int out_size) {
    const float* xn      = (const float*)d_in[0];
    const float* xe      = (const float*)d_in[1];
    const int*   iInd    = (const int*)d_in[2];
    const int*   jInd    = (const int*)d_in[3];
    const float* KNopen  = (const float*)d_in[4];
    const float* KEopen  = (const float*)d_in[5];
    const float* KNclose = (const float*)d_in[6];
    const float* KEclose = (const float*)d_in[7];
    const float* KN      = (const float*)d_in[8];
    const float* KE      = (const float*)d_in[9];
    const float* KD      = (const float*)d_in[10];
    float* out = (float*)d_out;
    (void)in_sizes; (void)n_in; (void)out_size;

    float *pXn, *pXe, *pZ, *pW, *pU, *pDiv;
    cudaGetSymbolAddress((void**)&pXn, g_Xn);
    cudaGetSymbolAddress((void**)&pXe, g_Xe);
    cudaGetSymbolAddress((void**)&pZ, g_Z);
    cudaGetSymbolAddress((void**)&pW, g_W);
    cudaGetSymbolAddress((void**)&pU, g_U);
    cudaGetSymbolAddress((void**)&pDiv, g_div);

    const int TB = 256;
    const int gN = (NN + TB - 1) / TB;             // 196
    const int gE = (NE + TB - 1) / TB;             // 3125
    const int gMM = (NN * 2 + TB - 1) / TB;        // 391
    const int gEB = ((NE * 16) + TB - 1) / TB;     // 50000

    k_open<<<gN, TB>>>(xn, KNopen, pXn, NN);
    k_open<<<gE, TB>>>(xe, KEopen, pXe, NE);

    for (int l = 0; l < NL; l++) {
        const float* Kn = KN + (size_t)l * C * C;
        const float* Ke = KE + (size_t)l * C * C;
        const float* Kd = KD + (size_t)l * C * C;

        k_zero<<<256, TB>>>();
        k_mmv3<<<gMM, TB>>>(pXn, Kn, pZ, NN);
        k_mmv3<<<gMM, TB>>>(pXn, Kd, pW, NN);
        k_stats<<<256, TB>>>(pW, NN, 2 * C);
        k_edgeA<<<2048, TB>>>(iInd, jInd);
        k_scales<<<1, 64>>>(0);
        k_edgeB<<<gEB, TB>>>(iInd, jInd);
        k_mmv3<<<gMM, TB>>>(pDiv, Ke, pU, NN);
        k_stats<<<256, TB>>>(pU, NN, 4 * C);
        k_scales<<<1, 64>>>(1);
        k_update<<<gN, TB>>>();
    }

    k_close<<<gN, TB>>>(KNclose, pXn, out, NN);
    k_close<<<gE, TB>>>(KEclose, pXe, out + (size_t)CIN * NN, NE);
}